// round 4
// baseline (speedup 1.0000x reference)
#include <cuda_runtime.h>

#define B 256
#define C 50000
#define D 512
#define ALPHA 0.5f

#define OH_SLICES 8                 // blocks per onehot row
#define NB_OH (B * OH_SLICES)       // 2048 onehot blocks
#define OH_ROW4 (C / 4)             // 12500 float4 per row
#define OH_PER_SLICE ((OH_ROW4 + OH_SLICES - 1) / OH_SLICES)  // 1563

#define COPY_PER_THREAD 8
#define NB_COPY ((C * D / 4) / (256 * COPY_PER_THREAD))  // 3125, exact
#define NB_PROD (NB_OH + NB_COPY)   // 5173 producer blocks
#define NB_FIX  B                   // 256 fixup blocks, last in grid
#define NB_TOTAL (NB_PROD + NB_FIX)

__device__ int g_labels[B];
__device__ unsigned int g_done = 0;   // producer completion counter
__device__ unsigned int g_fix  = 0;   // fixup completion counter (for reset)

__device__ __forceinline__ float4 ldcs4(const float4* p) {
    return __ldcs(p);
}

// One kernel, three roles by block range:
//   [0, NB_OH)            : onehot label scan
//   [NB_OH, NB_PROD)      : centers -> new_centers bulk copy (streaming)
//   [NB_PROD, NB_TOTAL)   : fixup — waits for all producers, then computes
//                           result[b] and rewrites touched new_centers rows.
__global__ void __launch_bounds__(256) center_loss_kernel(
    const float* __restrict__ x,
    const float* __restrict__ onehot,
    const float* __restrict__ centers,
    float* __restrict__ result,
    float* __restrict__ new_centers) {
    int blk = blockIdx.x;
    int tid = threadIdx.x;

    if (blk < NB_OH) {
        // ---- onehot scan ----
        int b = blk >> 3;
        int slice = blk & 7;
        const float4* row = reinterpret_cast<const float4*>(onehot) +
                            (size_t)b * OH_ROW4;
        int lo = slice * OH_PER_SLICE;
        int hi = lo + OH_PER_SLICE;
        if (hi > OH_ROW4) hi = OH_ROW4;
        int found = -1;
        for (int i = lo + tid; i < hi; i += 256) {
            float4 v = __ldcs(row + i);
            if (v.x != 0.0f) found = 4 * i + 0;
            if (v.y != 0.0f) found = 4 * i + 1;
            if (v.z != 0.0f) found = 4 * i + 2;
            if (v.w != 0.0f) found = 4 * i + 3;
        }
        if (found >= 0) g_labels[b] = found;
        // signal completion
        __syncthreads();
        __threadfence();
        if (tid == 0) atomicAdd(&g_done, 1u);
    } else if (blk < NB_PROD) {
        // ---- bulk copy, streaming hints ----
        int cb = blk - NB_OH;
        const float4* src = reinterpret_cast<const float4*>(centers);
        float4* dst = reinterpret_cast<float4*>(new_centers);
        size_t base = (size_t)cb * (256 * COPY_PER_THREAD) + tid;
        #pragma unroll
        for (int k = 0; k < COPY_PER_THREAD; k++) {
            size_t idx = base + (size_t)k * 256;
            __stcs(dst + idx, __ldcs(src + idx));
        }
        __syncthreads();
        __threadfence();
        if (tid == 0) atomicAdd(&g_done, 1u);
    } else {
        // ---- fixup ----
        int b = blk - NB_PROD;

        __shared__ float s_x[D];          // prefetched x[b] row
        __shared__ int s_lab[B];
        __shared__ int s_match[B];
        __shared__ int s_cnt;
        __shared__ int s_first;
        __shared__ float s_warp[8];

        // prefetch x row while producers finish (independent of them)
        const float* xb = x + (size_t)b * D;
        #pragma unroll
        for (int k = 0; k < D / 256; k++)
            s_x[tid + k * 256] = xb[tid + k * 256];
        if (tid == 0) { s_cnt = 0; s_first = B; }

        // wait for all producers
        if (tid == 0) {
            while (atomicAdd(&g_done, 0u) < NB_PROD) { }
        }
        __syncthreads();
        __threadfence();

        // coalesced label load + parallel match-list build
        s_lab[tid] = g_labels[tid];
        __syncthreads();
        int l = s_lab[b];
        if (s_lab[tid] == l) {
            int pos = atomicAdd(&s_cnt, 1);
            s_match[pos] = tid;
            atomicMin(&s_first, tid);
        }
        __syncthreads();

        const float* cl = centers + (size_t)l * D;

        // result[b] = || x[b] - centers[l] ||^2
        float acc = 0.0f;
        #pragma unroll
        for (int k = 0; k < D / 256; k++) {
            int d = tid + k * 256;
            float df = s_x[d] - cl[d];
            acc += df * df;
        }
        #pragma unroll
        for (int off = 16; off > 0; off >>= 1)
            acc += __shfl_down_sync(0xFFFFFFFFu, acc, off);
        if ((tid & 31) == 0) s_warp[tid >> 5] = acc;
        __syncthreads();
        if (tid == 0) {
            float tot = 0.0f;
            #pragma unroll
            for (int w = 0; w < 8; w++) tot += s_warp[w];
            result[b] = tot;
        }

        // lowest-indexed sample per class rewrites that class's row
        if (b == s_first) {
            int n = s_cnt;
            float inv = 1.0f / ((float)n + 1.0f);
            #pragma unroll
            for (int k = 0; k < D / 256; k++) {
                int d = tid + k * 256;
                float sx = 0.0f;
                for (int m = 0; m < n; m++)
                    sx += x[(size_t)s_match[m] * D + d];
                float c = cl[d];
                new_centers[(size_t)l * D + d] =
                    c - ALPHA * ((float)n * c - sx) * inv;
            }
        }

        // last fixup block resets counters for graph replay determinism
        __syncthreads();
        if (tid == 0) {
            unsigned int f = atomicAdd(&g_fix, 1u);
            if (f == NB_FIX - 1) {
                g_done = 0;
                g_fix = 0;
                __threadfence();
            }
        }
    }
}

extern "C" void kernel_launch(void* const* d_in, const int* in_sizes, int n_in,
                              void* d_out, int out_size) {
    const float* x       = (const float*)d_in[0];
    const float* onehot  = (const float*)d_in[1];
    const float* centers = (const float*)d_in[2];

    float* result      = (float*)d_out;        // [B, 1]
    float* new_centers = (float*)d_out + B;    // [C, D]

    center_loss_kernel<<<NB_TOTAL, 256>>>(x, onehot, centers,
                                          result, new_centers);
}

// round 5
// speedup vs baseline: 1.0282x; 1.0282x over previous
#include <cuda_runtime.h>

#define B 256
#define C 50000
#define D 512
#define ALPHA 0.5f

// ---- K1: onehot label scan ----
#define OH_SLICES 8
#define NB_OH (B * OH_SLICES)       // 2048 blocks
#define OH_ROW4 (C / 4)             // 12500 float4 per row
#define OH_PER_SLICE ((OH_ROW4 + OH_SLICES - 1) / OH_SLICES)  // 1563

// ---- K2: copy+fixup ----
// Each copy block: 256 threads x 8 float4 = 8192 floats = 16 rows of D=512.
#define COPY_PER_THREAD 8
#define ROWS_PER_BLOCK 16
#define NB_COPY ((C * D / 4) / (256 * COPY_PER_THREAD))  // 3125, exact
#define NB_K2 (NB_COPY + B)

__device__ int g_labels[B];

// K1: find the single nonzero column of each onehot row.
__global__ void __launch_bounds__(256) labels_kernel(
    const float* __restrict__ onehot) {
    int blk = blockIdx.x;
    int b = blk >> 3;
    int slice = blk & 7;
    const float4* row = reinterpret_cast<const float4*>(onehot) +
                        (size_t)b * OH_ROW4;
    int lo = slice * OH_PER_SLICE;
    int hi = lo + OH_PER_SLICE;
    if (hi > OH_ROW4) hi = OH_ROW4;
    int found = -1;
    for (int i = lo + threadIdx.x; i < hi; i += 256) {
        float4 v = row[i];
        if (v.x != 0.0f) found = 4 * i + 0;
        if (v.y != 0.0f) found = 4 * i + 1;
        if (v.z != 0.0f) found = 4 * i + 2;
        if (v.w != 0.0f) found = 4 * i + 3;
    }
    if (found >= 0) g_labels[b] = found;
}

// K2: blocks [0, NB_COPY): copy 16 center rows -> new_centers; blocks owning
// a labeled row overwrite it with the center-update formula.
//     blocks [NB_COPY, NB_COPY+B): result[b] = ||x[b]-centers[l_b]||^2.
__global__ void __launch_bounds__(256) copy_fixup_kernel(
    const float* __restrict__ x,
    const float* __restrict__ centers,
    float* __restrict__ result,
    float* __restrict__ new_centers) {
    int blk = blockIdx.x;
    int tid = threadIdx.x;

    if (blk < NB_COPY) {
        __shared__ int s_lab[B];
        __shared__ unsigned int s_mask;   // bit ri: row r0+ri is touched

        s_lab[tid] = g_labels[tid];
        if (tid == 0) s_mask = 0u;
        __syncthreads();

        int r0 = blk * ROWS_PER_BLOCK;
        int l = s_lab[tid];
        if (l >= r0 && l < r0 + ROWS_PER_BLOCK)
            atomicOr(&s_mask, 1u << (l - r0));
        __syncthreads();

        // ---- fast path: bulk copy (always executed) ----
        const float4* src = reinterpret_cast<const float4*>(centers);
        float4* dst = reinterpret_cast<float4*>(new_centers);
        size_t base = (size_t)blk * (256 * COPY_PER_THREAD) + tid;
        #pragma unroll
        for (int k = 0; k < COPY_PER_THREAD; k++) {
            size_t idx = base + (size_t)k * 256;
            dst[idx] = src[idx];
        }

        // ---- rare path: overwrite touched rows with fixup values ----
        if (s_mask != 0u) {
            __syncthreads();   // order copy writes before overwrite
            unsigned int mask = s_mask;
            while (mask) {
                int ri = __ffs(mask) - 1;
                mask &= mask - 1;
                int row = r0 + ri;
                // gather matches: count n and x-sums for this thread's 2 elems
                int n = 0;
                float sx0 = 0.0f, sx1 = 0.0f;
                for (int m = 0; m < B; m++) {
                    if (s_lab[m] == row) {
                        n++;
                        const float* xm = x + (size_t)m * D;
                        sx0 += xm[tid];
                        sx1 += xm[tid + 256];
                    }
                }
                float inv = 1.0f / ((float)n + 1.0f);
                float fn = (float)n;
                size_t rb = (size_t)row * D;
                float c0 = centers[rb + tid];
                float c1 = centers[rb + tid + 256];
                new_centers[rb + tid]       = c0 - ALPHA * (fn * c0 - sx0) * inv;
                new_centers[rb + tid + 256] = c1 - ALPHA * (fn * c1 - sx1) * inv;
            }
        }
    } else {
        // ---- result blocks: result[b] = ||x[b] - centers[l]||^2 ----
        int b = blk - NB_COPY;
        __shared__ float s_warp[8];
        int l = g_labels[b];
        const float* xb = x + (size_t)b * D;
        const float* cl = centers + (size_t)l * D;
        float acc = 0.0f;
        #pragma unroll
        for (int k = 0; k < D / 256; k++) {
            int d = tid + k * 256;
            float df = xb[d] - cl[d];
            acc += df * df;
        }
        #pragma unroll
        for (int off = 16; off > 0; off >>= 1)
            acc += __shfl_down_sync(0xFFFFFFFFu, acc, off);
        if ((tid & 31) == 0) s_warp[tid >> 5] = acc;
        __syncthreads();
        if (tid == 0) {
            float tot = 0.0f;
            #pragma unroll
            for (int w = 0; w < 8; w++) tot += s_warp[w];
            result[b] = tot;
        }
    }
}

extern "C" void kernel_launch(void* const* d_in, const int* in_sizes, int n_in,
                              void* d_out, int out_size) {
    const float* x       = (const float*)d_in[0];
    const float* onehot  = (const float*)d_in[1];
    const float* centers = (const float*)d_in[2];

    float* result      = (float*)d_out;        // [B, 1]
    float* new_centers = (float*)d_out + B;    // [C, D]

    labels_kernel<<<NB_OH, 256>>>(onehot);
    copy_fixup_kernel<<<NB_K2, 256>>>(x, centers, result, new_centers);
}